// round 6
// baseline (speedup 1.0000x reference)
#include <cuda_runtime.h>
#include <cuda_bf16.h>
#include <cstdint>

#define NN 30000
#define TT 4
#define FF 128
#define HH 8
#define DD 16

// Scratch (no cudaMalloc allowed)
__device__ float g_node_p[NN * FF];        // [N,F]
__device__ float g_edge_p[NN * TT * FF];   // [N,T,F]
__device__ int   g_lists[TT][NN];
__device__ int   g_counts[TT];

// ---------------------------------------------------------------------------
__global__ void k_zero() { if (threadIdx.x < TT) g_counts[threadIdx.x] = 0; }

__global__ void k_scatter(const int* __restrict__ mask, int n) {
    int i = blockIdx.x * blockDim.x + threadIdx.x;
    if (i < n) {
        int t = mask[i];
        int p = atomicAdd(&g_counts[t], 1);
        g_lists[t][p] = i;
    }
}

// ---------------------------------------------------------------------------
// Tensor-core grouped GEMM, two-phase 3-tile SMEM schedule for 2 CTAs/SM.
// C[i,g] = sum_f A[i,f] * M[g,f];  C = Ah*Mh + Al*Mh + Ah*Ml (bf16 3-term).
// Tiles: 128 rows x 128 bf16, row padded to 136 bf16 (272B = 68 words).
// Fragment loads via ldmatrix.x4 (conflict-free with the 68-word stride).
// ---------------------------------------------------------------------------
#define RSTRIDE 136
#define RWORDS 68
#define TILE_BYTES (128 * RSTRIDE * 2)    // 34816
#define SM_AHI 0
#define SM_MHI TILE_BYTES
#define SM_X   (2 * TILE_BYTES)           // Al in phase 1, Ml in phase 2
#define SM_ROWS (3 * TILE_BYTES)
#define SMEM_BYTES (3 * TILE_BYTES + 512)

__device__ __forceinline__ uint32_t pk(__nv_bfloat16 a, __nv_bfloat16 b) {
    __nv_bfloat162 t(a, b);
    return *(uint32_t*)&t;
}

__device__ __forceinline__ void split4(float4 v, uint2& hi, uint2& lo) {
    __nv_bfloat16 h0 = __float2bfloat16_rn(v.x); float l0 = v.x - __bfloat162float(h0);
    __nv_bfloat16 h1 = __float2bfloat16_rn(v.y); float l1 = v.y - __bfloat162float(h1);
    __nv_bfloat16 h2 = __float2bfloat16_rn(v.z); float l2 = v.z - __bfloat162float(h2);
    __nv_bfloat16 h3 = __float2bfloat16_rn(v.w); float l3 = v.w - __bfloat162float(h3);
    hi = make_uint2(pk(h0, h1), pk(h2, h3));
    lo = make_uint2(pk(__float2bfloat16_rn(l0), __float2bfloat16_rn(l1)),
                    pk(__float2bfloat16_rn(l2), __float2bfloat16_rn(l3)));
}

__device__ __forceinline__ void mma16816(float* c, const uint32_t* a, const uint32_t* b) {
    asm volatile(
        "mma.sync.aligned.m16n8k16.row.col.f32.bf16.bf16.f32 "
        "{%0,%1,%2,%3}, {%4,%5,%6,%7}, {%8,%9}, {%0,%1,%2,%3};"
        : "+f"(c[0]), "+f"(c[1]), "+f"(c[2]), "+f"(c[3])
        : "r"(a[0]), "r"(a[1]), "r"(a[2]), "r"(a[3]), "r"(b[0]), "r"(b[1]));
}

__device__ __forceinline__ void ldm_x4(uint32_t& r0, uint32_t& r1, uint32_t& r2,
                                       uint32_t& r3, uint32_t saddr) {
    asm volatile("ldmatrix.sync.aligned.m8n8.x4.shared.b16 {%0,%1,%2,%3}, [%4];"
                 : "=r"(r0), "=r"(r1), "=r"(r2), "=r"(r3) : "r"(saddr));
}

// One accumulation term: acc[2][8][4] += A(128x128) * B(128x128)^T fragments.
// laneoff = byte offset encoding lane's (row, wordcol) within any matrix group.
__device__ __forceinline__ void compute_term(
    uint32_t Abase, uint32_t Bbase, uint32_t laneoff, int m0, int n0,
    float acc[2][8][4])
{
    uint32_t a0 = Abase + (uint32_t)m0 * 272u + laneoff;
    uint32_t a1 = a0 + 16u * 272u;
    uint32_t b0 = Bbase + (uint32_t)n0 * 272u + laneoff;
#pragma unroll
    for (int k0 = 0; k0 < 8; k0++) {
        const uint32_t koff = (uint32_t)k0 * 32u;
        uint32_t a[2][4];
        ldm_x4(a[0][0], a[0][1], a[0][2], a[0][3], a0 + koff);
        ldm_x4(a[1][0], a[1][1], a[1][2], a[1][3], a1 + koff);
#pragma unroll
        for (int p = 0; p < 4; p++) {
            uint32_t b0e, b0o, b1e, b1o;
            ldm_x4(b0e, b0o, b1e, b1o, b0 + (uint32_t)p * (16u * 272u) + koff);
            uint32_t be[2] = { b0e, b1e };
            uint32_t bo[2] = { b0o, b1o };
            mma16816(acc[0][2 * p],     a[0], be);
            mma16816(acc[0][2 * p + 1], a[0], bo);
            mma16816(acc[1][2 * p],     a[1], be);
            mma16816(acc[1][2 * p + 1], a[1], bo);
        }
    }
}

__global__ __launch_bounds__(256, 2) void k_gemm_mma(
    const float* __restrict__ feature,    // [N,F]
    const float* __restrict__ edge_fea,   // [N,T,F]
    const float* __restrict__ node_proj,  // [T,F,F]
    const float* __restrict__ edge_proj)  // [T*T,F,F]
{
    extern __shared__ char smem[];
    const int t = blockIdx.y;
    const int j = blockIdx.z;
    const int cnt = g_counts[t];
    const int start = blockIdx.x * 128;
    if (start >= cnt) return;

    const int tid  = threadIdx.x;
    const int wid  = tid >> 5;
    const int lane = tid & 31;

    const float* M = (j == 4) ? (node_proj + (size_t)t * FF * FF)
                              : (edge_proj + ((size_t)t * TT + j) * FF * FF);

    int* rows = (int*)(smem + SM_ROWS);
    if (tid < 128) {
        int idx = start + tid;
        rows[tid] = (idx < cnt) ? g_lists[t][idx] : -1;
    }
    __syncthreads();

    // ---- stage phase 1: Ah -> SM_AHI, Al -> SM_X, Mh -> SM_MHI ----
    {
        const int half = tid >> 7;
        const int row  = tid & 127;
        const uint32_t rb = (uint32_t)row * (RSTRIDE * 2);
        if (half == 0) {
            int r = rows[row];
            const float* src = (r < 0) ? nullptr
                : ((j == 4) ? (feature + (size_t)r * FF)
                            : (edge_fea + ((size_t)r * TT + j) * FF));
#pragma unroll
            for (int c4 = 0; c4 < 32; c4++) {
                float4 v = src ? *(const float4*)(src + c4 * 4)
                               : make_float4(0.f, 0.f, 0.f, 0.f);
                uint2 hi, lo;
                split4(v, hi, lo);
                *(uint2*)(smem + SM_AHI + rb + c4 * 8) = hi;
                *(uint2*)(smem + SM_X   + rb + c4 * 8) = lo;
            }
        } else {
            const float* src = M + (size_t)row * FF;
#pragma unroll
            for (int c4 = 0; c4 < 32; c4++) {
                float4 v = *(const float4*)(src + c4 * 4);
                __nv_bfloat16 h0 = __float2bfloat16_rn(v.x);
                __nv_bfloat16 h1 = __float2bfloat16_rn(v.y);
                __nv_bfloat16 h2 = __float2bfloat16_rn(v.z);
                __nv_bfloat16 h3 = __float2bfloat16_rn(v.w);
                *(uint2*)(smem + SM_MHI + rb + c4 * 8) =
                    make_uint2(pk(h0, h1), pk(h2, h3));
            }
        }
    }
    __syncthreads();

    // warp tiles: 4(m) x 2(n); warp tile 32m x 64n
    const int m0 = (wid >> 1) * 32;
    const int n0 = (wid & 1) * 64;
    const int fr = lane >> 2;
    const int fc = lane & 3;
    const uint32_t laneoff = (uint32_t)(lane & 15) * 272u + (uint32_t)(lane >> 4) * 16u;

    uint32_t sb;
    {
        uint64_t g = (uint64_t)__cvta_generic_to_shared(smem);
        sb = (uint32_t)g;
    }

    float acc[2][8][4];
#pragma unroll
    for (int mt = 0; mt < 2; mt++)
#pragma unroll
        for (int nt = 0; nt < 8; nt++)
#pragma unroll
            for (int q = 0; q < 4; q++) acc[mt][nt][q] = 0.f;

    // phase 1 terms: Ah*Mh and Al*Mh
    compute_term(sb + SM_AHI, sb + SM_MHI, laneoff, m0, n0, acc);
    compute_term(sb + SM_X,   sb + SM_MHI, laneoff, m0, n0, acc);
    __syncthreads();

    // ---- restage: SM_X <- Ml (lo part of M) ----
    {
        const int row = tid >> 1;
        const int c0  = (tid & 1) * 16;
        const float* src = M + (size_t)row * FF;
        const uint32_t rb = (uint32_t)row * (RSTRIDE * 2);
#pragma unroll
        for (int c4 = 0; c4 < 16; c4++) {
            float4 v = *(const float4*)(src + (c0 + c4) * 4);
            uint2 hi, lo;
            split4(v, hi, lo);
            *(uint2*)(smem + SM_X + rb + (c0 + c4) * 8) = lo;
        }
    }
    __syncthreads();

    // phase 2 term: Ah*Ml
    compute_term(sb + SM_AHI, sb + SM_X, laneoff, m0, n0, acc);

    // ---- epilogue ----
#pragma unroll
    for (int mt = 0; mt < 2; mt++) {
#pragma unroll
        for (int half = 0; half < 2; half++) {
            int mrow = m0 + mt * 16 + half * 8 + fr;
            int r = rows[mrow];
            if (r < 0) continue;
            float* dst = (j == 4) ? (g_node_p + (size_t)r * FF)
                                  : (g_edge_p + ((size_t)r * TT + j) * FF);
#pragma unroll
            for (int nt = 0; nt < 8; nt++) {
                *(float2*)(dst + n0 + nt * 8 + fc * 2) =
                    make_float2(acc[mt][nt][half * 2], acc[mt][nt][half * 2 + 1]);
            }
        }
    }
}

// ---------------------------------------------------------------------------
// Scores + softmax over HEAD axis. One warp/node, lane = t*8+h.
// ---------------------------------------------------------------------------
__global__ void k_attn(float* __restrict__ out, int n) {
    int warp = (int)((blockIdx.x * blockDim.x + threadIdx.x) >> 5);
    int lane = threadIdx.x & 31;
    if (warp >= n) return;
    int t = lane >> 3;
    int h = lane & 7;

    const float* np = g_node_p + (size_t)warp * FF + h * DD;
    const float* ep = g_edge_p + ((size_t)warp * TT + t) * FF + h * DD;

    float s = 0.f;
#pragma unroll
    for (int q = 0; q < 4; q++) {
        float4 a = *(const float4*)(np + q * 4);
        float4 b = *(const float4*)(ep + q * 4);
        s += a.x * b.x + a.y * b.y + a.z * b.z + a.w * b.w;
    }
    s *= 0.25f;  // 1/sqrt(16)

    float m = s;
#pragma unroll
    for (int o = 4; o >= 1; o >>= 1)
        m = fmaxf(m, __shfl_xor_sync(0xffffffffu, m, o, 8));
    float e = expf(s - m);
    float sum = e;
#pragma unroll
    for (int o = 4; o >= 1; o >>= 1)
        sum += __shfl_xor_sync(0xffffffffu, sum, o, 8);

    out[(size_t)warp * (TT * HH) + lane] = e / sum;
}

// ---------------------------------------------------------------------------
extern "C" void kernel_launch(void* const* d_in, const int* in_sizes, int n_in,
                              void* d_out, int out_size) {
    const float* feature   = (const float*)d_in[0];
    const float* edge_fea  = (const float*)d_in[1];
    const int*   mask      = (const int*)d_in[2];
    const float* node_proj = (const float*)d_in[3];
    const float* edge_proj = (const float*)d_in[4];
    float* out = (float*)d_out;

    const int n = in_sizes[2];

    static int smem_set = 0;
    if (!smem_set) {
        cudaFuncSetAttribute(k_gemm_mma, cudaFuncAttributeMaxDynamicSharedMemorySize, SMEM_BYTES);
        smem_set = 1;
    }

    k_zero<<<1, 32>>>();
    k_scatter<<<(n + 255) / 256, 256>>>(mask, n);

    dim3 grid((n + 127) / 128, TT, 5);
    k_gemm_mma<<<grid, 256, SMEM_BYTES>>>(feature, edge_fea, node_proj, edge_proj);

    k_attn<<<(n + 7) / 8, 256>>>(out, n);
}

// round 7
// speedup vs baseline: 1.1243x; 1.1243x over previous
#include <cuda_runtime.h>
#include <cuda_bf16.h>
#include <cstdint>

#define NN 30000
#define TT 4
#define FF 128
#define HH 8
#define DD 16

// Scratch (no cudaMalloc allowed)
__device__ float g_node_p[NN * FF];        // [N,F]
__device__ int   g_lists[TT][NN];
__device__ int   g_counts[TT];

// ---------------------------------------------------------------------------
__global__ void k_zero() { if (threadIdx.x < TT) g_counts[threadIdx.x] = 0; }

__global__ void k_scatter(const int* __restrict__ mask, int n) {
    int i = blockIdx.x * blockDim.x + threadIdx.x;
    if (i < n) {
        int t = mask[i];
        int p = atomicAdd(&g_counts[t], 1);
        g_lists[t][p] = i;
    }
}

// ---------------------------------------------------------------------------
// GEMM core: C[i,g] = sum_f A[i,f]*M[g,f];  C = Ah*Mh + Al*Mh + Ah*Ml.
// 4 SMEM tiles 128x128 bf16, rows padded to 136 bf16 (272 B), occ 1.
// ldmatrix.x4 fragment loads (conflict-free; numerics validated in R6).
// ---------------------------------------------------------------------------
#define RSTRIDE 136
#define TILE_BYTES (128 * RSTRIDE * 2)    // 34816
#define SM_AHI 0
#define SM_ALO TILE_BYTES
#define SM_MHI (2 * TILE_BYTES)
#define SM_MLO (3 * TILE_BYTES)
#define SM_ROWS (4 * TILE_BYTES)          // 128 ints
#define SM_SCORE (SM_ROWS + 512)          // 128*8 floats
#define SMEM_BYTES (SM_SCORE + 4096)

__device__ __forceinline__ uint32_t pk(__nv_bfloat16 a, __nv_bfloat16 b) {
    __nv_bfloat162 t(a, b);
    return *(uint32_t*)&t;
}

__device__ __forceinline__ void split4(float4 v, uint2& hi, uint2& lo) {
    __nv_bfloat16 h0 = __float2bfloat16_rn(v.x); float l0 = v.x - __bfloat162float(h0);
    __nv_bfloat16 h1 = __float2bfloat16_rn(v.y); float l1 = v.y - __bfloat162float(h1);
    __nv_bfloat16 h2 = __float2bfloat16_rn(v.z); float l2 = v.z - __bfloat162float(h2);
    __nv_bfloat16 h3 = __float2bfloat16_rn(v.w); float l3 = v.w - __bfloat162float(h3);
    hi = make_uint2(pk(h0, h1), pk(h2, h3));
    lo = make_uint2(pk(__float2bfloat16_rn(l0), __float2bfloat16_rn(l1)),
                    pk(__float2bfloat16_rn(l2), __float2bfloat16_rn(l3)));
}

__device__ __forceinline__ void mma16816(float* c, const uint32_t* a, const uint32_t* b) {
    asm volatile(
        "mma.sync.aligned.m16n8k16.row.col.f32.bf16.bf16.f32 "
        "{%0,%1,%2,%3}, {%4,%5,%6,%7}, {%8,%9}, {%0,%1,%2,%3};"
        : "+f"(c[0]), "+f"(c[1]), "+f"(c[2]), "+f"(c[3])
        : "r"(a[0]), "r"(a[1]), "r"(a[2]), "r"(a[3]), "r"(b[0]), "r"(b[1]));
}

__device__ __forceinline__ void ldm_x4(uint32_t& r0, uint32_t& r1, uint32_t& r2,
                                       uint32_t& r3, uint32_t saddr) {
    asm volatile("ldmatrix.sync.aligned.m8n8.x4.shared.b16 {%0,%1,%2,%3}, [%4];"
                 : "=r"(r0), "=r"(r1), "=r"(r2), "=r"(r3) : "r"(saddr));
}

__device__ __forceinline__ void compute_term(
    uint32_t Abase, uint32_t Bbase, uint32_t laneoff, int m0, int n0,
    float acc[2][8][4])
{
    uint32_t a0 = Abase + (uint32_t)m0 * 272u + laneoff;
    uint32_t a1 = a0 + 16u * 272u;
    uint32_t b0 = Bbase + (uint32_t)n0 * 272u + laneoff;
#pragma unroll
    for (int k0 = 0; k0 < 8; k0++) {
        const uint32_t koff = (uint32_t)k0 * 32u;
        uint32_t a[2][4];
        ldm_x4(a[0][0], a[0][1], a[0][2], a[0][3], a0 + koff);
        ldm_x4(a[1][0], a[1][1], a[1][2], a[1][3], a1 + koff);
#pragma unroll
        for (int p = 0; p < 4; p++) {
            uint32_t b0e, b0o, b1e, b1o;
            ldm_x4(b0e, b0o, b1e, b1o, b0 + (uint32_t)p * (16u * 272u) + koff);
            uint32_t be[2] = { b0e, b1e };
            uint32_t bo[2] = { b0o, b1o };
            mma16816(acc[0][2 * p],     a[0], be);
            mma16816(acc[0][2 * p + 1], a[0], bo);
            mma16816(acc[1][2 * p],     a[1], be);
            mma16816(acc[1][2 * p + 1], a[1], bo);
        }
    }
}

// stage: threads 0-127 convert A row (hi->AHI, lo->ALO); 128-255 M row (hi/lo).
__device__ __forceinline__ void stage_tiles(
    char* smem, const int* rows, const float* __restrict__ Asrc_base,
    size_t Astride, const float* __restrict__ M, int tid)
{
    const int half = tid >> 7;
    const int row  = tid & 127;
    const uint32_t rb = (uint32_t)row * (RSTRIDE * 2);
    const float* src;
    char *dhi, *dlo;
    if (half == 0) {
        int r = rows[row];
        src = (r < 0) ? nullptr : (Asrc_base + (size_t)r * Astride);
        dhi = smem + SM_AHI; dlo = smem + SM_ALO;
    } else {
        src = M + (size_t)row * FF;
        dhi = smem + SM_MHI; dlo = smem + SM_MLO;
    }
#pragma unroll
    for (int c4 = 0; c4 < 32; c4++) {
        float4 v = src ? *(const float4*)(src + c4 * 4)
                       : make_float4(0.f, 0.f, 0.f, 0.f);
        uint2 hi, lo;
        split4(v, hi, lo);
        *(uint2*)(dhi + rb + c4 * 8) = hi;
        *(uint2*)(dlo + rb + c4 * 8) = lo;
    }
}

// ---------------------------------------------------------------------------
// Node projection GEMM: writes g_node_p[r, :].
// ---------------------------------------------------------------------------
__global__ __launch_bounds__(256, 1) void k_gemm_node(
    const float* __restrict__ feature, const float* __restrict__ node_proj)
{
    extern __shared__ char smem[];
    const int t = blockIdx.y;
    const int cnt = g_counts[t];
    const int start = blockIdx.x * 128;
    if (start >= cnt) return;

    const int tid = threadIdx.x, wid = tid >> 5, lane = tid & 31;
    int* rows = (int*)(smem + SM_ROWS);
    if (tid < 128) {
        int idx = start + tid;
        rows[tid] = (idx < cnt) ? g_lists[t][idx] : -1;
    }
    __syncthreads();

    stage_tiles(smem, rows, feature, FF, node_proj + (size_t)t * FF * FF, tid);
    __syncthreads();

    const int m0 = (wid >> 1) * 32, n0 = (wid & 1) * 64;
    const int fr = lane >> 2, fc = lane & 3;
    const uint32_t laneoff = (uint32_t)(lane & 15) * 272u + (uint32_t)(lane >> 4) * 16u;
    uint32_t sb = (uint32_t)(uint64_t)__cvta_generic_to_shared(smem);

    float acc[2][8][4];
#pragma unroll
    for (int mt = 0; mt < 2; mt++)
#pragma unroll
        for (int nt = 0; nt < 8; nt++)
#pragma unroll
            for (int q = 0; q < 4; q++) acc[mt][nt][q] = 0.f;

    compute_term(sb + SM_AHI, sb + SM_MHI, laneoff, m0, n0, acc);
    compute_term(sb + SM_ALO, sb + SM_MHI, laneoff, m0, n0, acc);
    compute_term(sb + SM_AHI, sb + SM_MLO, laneoff, m0, n0, acc);

#pragma unroll
    for (int mt = 0; mt < 2; mt++) {
#pragma unroll
        for (int half = 0; half < 2; half++) {
            int r = rows[m0 + mt * 16 + half * 8 + fr];
            if (r < 0) continue;
            float* dst = g_node_p + (size_t)r * FF;
#pragma unroll
            for (int nt = 0; nt < 8; nt++)
                *(float2*)(dst + n0 + nt * 8 + fc * 2) =
                    make_float2(acc[mt][nt][half * 2], acc[mt][nt][half * 2 + 1]);
        }
    }
}

// ---------------------------------------------------------------------------
// Edge projection GEMM with FUSED score + softmax epilogue.
// Block computes edge_p tile for (type t, slot j) and directly emits
// out[r, j, h] = softmax_h( <node_p[r,h,:], edge_p[r,j,h,:]> / 4 ).
// ---------------------------------------------------------------------------
__global__ __launch_bounds__(256, 1) void k_gemm_edge(
    const float* __restrict__ edge_fea, const float* __restrict__ edge_proj,
    float* __restrict__ out)
{
    extern __shared__ char smem[];
    const int t = blockIdx.y;
    const int j = blockIdx.z;
    const int cnt = g_counts[t];
    const int start = blockIdx.x * 128;
    if (start >= cnt) return;

    const int tid = threadIdx.x, wid = tid >> 5, lane = tid & 31;
    int* rows = (int*)(smem + SM_ROWS);
    float* ss = (float*)(smem + SM_SCORE);   // [128][8] scores
    if (tid < 128) {
        int idx = start + tid;
        rows[tid] = (idx < cnt) ? g_lists[t][idx] : -1;
    }
    __syncthreads();

    stage_tiles(smem, rows, edge_fea + j * FF, (size_t)TT * FF,
                edge_proj + ((size_t)t * TT + j) * FF * FF, tid);
    __syncthreads();

    const int m0 = (wid >> 1) * 32, n0 = (wid & 1) * 64;
    const int fr = lane >> 2, fc = lane & 3;
    const uint32_t laneoff = (uint32_t)(lane & 15) * 272u + (uint32_t)(lane >> 4) * 16u;
    uint32_t sb = (uint32_t)(uint64_t)__cvta_generic_to_shared(smem);

    float acc[2][8][4];
#pragma unroll
    for (int mt = 0; mt < 2; mt++)
#pragma unroll
        for (int nt = 0; nt < 8; nt++)
#pragma unroll
            for (int q = 0; q < 4; q++) acc[mt][nt][q] = 0.f;

    compute_term(sb + SM_AHI, sb + SM_MHI, laneoff, m0, n0, acc);
    compute_term(sb + SM_ALO, sb + SM_MHI, laneoff, m0, n0, acc);
    compute_term(sb + SM_AHI, sb + SM_MLO, laneoff, m0, n0, acc);
    __syncthreads();   // tiles no longer needed; reuse as node_p floats

    // ---- stage node_p rows into SMEM: nf[128][132] floats at offset 0 ----
    float* nf = (float*)smem;
#pragma unroll
    for (int s = 0; s < 16; s++) {
        int idx = tid + s * 256;          // float4 slot 0..4095
        int row = idx >> 5, q = idx & 31;
        int r = rows[row];
        float4 v = (r >= 0) ? *(const float4*)(g_node_p + (size_t)r * FF + q * 4)
                            : make_float4(0.f, 0.f, 0.f, 0.f);
        *(float4*)(nf + row * 132 + q * 4) = v;
    }
    __syncthreads();

    // ---- fused score: per quad, dot D-fragment cols against node_p ----
    const int hbase = (wid & 1) * 4;      // this warp's 4 heads
#pragma unroll
    for (int mt = 0; mt < 2; mt++) {
#pragma unroll
        for (int half = 0; half < 2; half++) {
            const int mrow = m0 + mt * 16 + half * 8 + fr;
            const float* nrow = nf + mrow * 132;
#pragma unroll
            for (int hh = 0; hh < 4; hh++) {
                float p = 0.f;
#pragma unroll
                for (int nt2 = 0; nt2 < 2; nt2++) {
                    const int nt = hh * 2 + nt2;
                    const int c = n0 + nt * 8 + fc * 2;
                    p += acc[mt][nt][half * 2]     * nrow[c]
                       + acc[mt][nt][half * 2 + 1] * nrow[c + 1];
                }
                p += __shfl_xor_sync(0xffffffffu, p, 1);
                p += __shfl_xor_sync(0xffffffffu, p, 2);
                if (fc == 0) ss[mrow * 8 + hbase + hh] = p * 0.25f;
            }
        }
    }
    __syncthreads();

    // ---- softmax over 8 heads, write out[r, j, :] ----
    if (tid < 128) {
        int r = rows[tid];
        if (r >= 0) {
            float v[HH];
            float m = -1e30f;
#pragma unroll
            for (int h = 0; h < HH; h++) { v[h] = ss[tid * 8 + h]; m = fmaxf(m, v[h]); }
            float sum = 0.f;
#pragma unroll
            for (int h = 0; h < HH; h++) { v[h] = expf(v[h] - m); sum += v[h]; }
            float inv = 1.f / sum;
            float* dst = out + (size_t)r * (TT * HH) + j * HH;
#pragma unroll
            for (int h = 0; h < HH; h += 4)
                *(float4*)(dst + h) = make_float4(v[h] * inv, v[h + 1] * inv,
                                                  v[h + 2] * inv, v[h + 3] * inv);
        }
    }
}

// ---------------------------------------------------------------------------
extern "C" void kernel_launch(void* const* d_in, const int* in_sizes, int n_in,
                              void* d_out, int out_size) {
    const float* feature   = (const float*)d_in[0];
    const float* edge_fea  = (const float*)d_in[1];
    const int*   mask      = (const int*)d_in[2];
    const float* node_proj = (const float*)d_in[3];
    const float* edge_proj = (const float*)d_in[4];
    float* out = (float*)d_out;

    const int n = in_sizes[2];

    static int smem_set = 0;
    if (!smem_set) {
        cudaFuncSetAttribute(k_gemm_node, cudaFuncAttributeMaxDynamicSharedMemorySize, SMEM_BYTES);
        cudaFuncSetAttribute(k_gemm_edge, cudaFuncAttributeMaxDynamicSharedMemorySize, SMEM_BYTES);
        smem_set = 1;
    }

    k_zero<<<1, 32>>>();
    k_scatter<<<(n + 255) / 256, 256>>>(mask, n);

    dim3 gn((n + 127) / 128, TT);
    k_gemm_node<<<gn, 256, SMEM_BYTES>>>(feature, node_proj);

    dim3 ge((n + 127) / 128, TT, TT);
    k_gemm_edge<<<ge, 256, SMEM_BYTES>>>(edge_fea, edge_proj, out);
}